// round 6
// baseline (speedup 1.0000x reference)
#include <cuda_runtime.h>
#include <cuda_bf16.h>
#include <cstdint>

// MatrixExpander: out(16,16,512,512) = kron(A(16,16,64,64), ones(8,8)), fp32.
//
// Established across R1-R5: the job is sink-bound at the SM->LTS write cap
// (~6.3 TB/s, path-independent). R6 keeps the winning smem->TMA bulk-store
// design (R2) and shaves fixed costs:
//   - 2 ADJACENT tiles per CTA -> ONE contiguous 32 KB bulk store
//   - 8192 CTAs instead of 16384 (half the scheduling + command overhead)
// Tile c covers out[c*4096 .. c*4096+4096): 8 copies of expanded A-row c.

__device__ __forceinline__ uint32_t smem_u32(const void* p) {
    uint32_t a;
    asm("{ .reg .u64 t; cvta.to.shared.u64 t, %1; cvt.u32.u64 %0, t; }"
        : "=r"(a) : "l"(p));
    return a;
}

__global__ __launch_bounds__(256)
void expander_tma2_kernel(const float* __restrict__ A, float* __restrict__ out)
{
    // Two 16 KB tiles back-to-back = one contiguous 32 KB span.
    __shared__ __align__(128) float4 buf[2048];

    const uint32_t cta  = blockIdx.x;        // [0, 8192)
    const uint32_t t    = threadIdx.x;       // [0, 256)
    const uint32_t half = t >> 7;            // 0 -> tile 2*cta, 1 -> tile 2*cta+1
    const uint32_t l    = t & 127u;          // lane within half

    const uint32_t c = (cta << 1) | half;    // tile id [0, 16384)

    // Thread handles float4 slots 8l..8l+7 of its tile.
    // Slot f (within tile row pattern) -> A col (f & 127) >> 1, so slots
    // 8l..8l+7 need A cols 4l..4l+3 (two slots per A value). One LDG.128.
    const float4 av = *reinterpret_cast<const float4*>(
        A + (c << 6) + ((4u * l) & 63u));

    float4* b = buf + (half << 10) + (l << 3);
    const float4 vx = make_float4(av.x, av.x, av.x, av.x);
    const float4 vy = make_float4(av.y, av.y, av.y, av.y);
    const float4 vz = make_float4(av.z, av.z, av.z, av.z);
    const float4 vw = make_float4(av.w, av.w, av.w, av.w);
    b[0] = vx;  b[1] = vx;
    b[2] = vy;  b[3] = vy;
    b[4] = vz;  b[5] = vz;
    b[6] = vw;  b[7] = vw;

    __syncthreads();

    if (t == 0) {
        asm volatile("fence.proxy.async.shared::cta;" ::: "memory");
        const uint32_t s = smem_u32(buf);
        const float* dst = out + ((size_t)cta << 13);   // cta * 8192 floats = 32 KB
        asm volatile(
            "cp.async.bulk.global.shared::cta.bulk_group [%0], [%1], %2;"
            :: "l"(dst), "r"(s), "n"(32768) : "memory");
        asm volatile("cp.async.bulk.commit_group;" ::: "memory");
        asm volatile("cp.async.bulk.wait_group 0;" ::: "memory");
    }
}

extern "C" void kernel_launch(void* const* d_in, const int* in_sizes, int n_in,
                              void* d_out, int out_size)
{
    const float* A = (const float*)d_in[0];   // (16,16,64,64) fp32
    float* out = (float*)d_out;               // (16,16,512,512) fp32

    // 8192 CTAs x 32 KB = 256 MiB output
    expander_tma2_kernel<<<8192, 256>>>(A, out);
}

// round 7
// speedup vs baseline: 1.5438x; 1.5438x over previous
#include <cuda_runtime.h>
#include <cuda_bf16.h>
#include <cstdint>

// MatrixExpander: out(16,16,512,512) = kron(A(16,16,64,64), ones(8,8)), fp32.
//
// Final form: tile-per-CTA smem->TMA bulk store (R2 winner) with a
// CONFLICT-FREE smem fill (R6 showed stride-128B STS saturates the smem
// crossbar at 85% L1 and regresses 45%).
//
// Tile c in [0,16384): out[c*4096 .. +4096) = 8 copies of the 512-float
// expanded row of A-row c, where expanded[j] = A[c*64 + j/8].
//
// Fill layout: thread t writes float4 slots {t, t+256, t+512, t+768}.
//   - lane stride 16 B -> fully coalesced, zero bank conflicts
//   - slot f needs A col (f & 127) >> 1; for all four slots of thread t this
//     is the SAME col (t & 127) >> 1 -> one scalar load, one splat, 4 STS.128.

__device__ __forceinline__ uint32_t smem_u32(const void* p) {
    uint32_t a;
    asm("{ .reg .u64 t; cvta.to.shared.u64 t, %1; cvt.u32.u64 %0, t; }"
        : "=r"(a) : "l"(p));
    return a;
}

__global__ __launch_bounds__(256)
void expander_tma_kernel(const float* __restrict__ A, float* __restrict__ out)
{
    __shared__ __align__(128) float4 buf[1024];   // 16 KB = 8 output rows

    const uint32_t c = blockIdx.x;   // tile id in [0, 16384)
    const uint32_t t = threadIdx.x;  // [0, 256)

    // One A value per thread (pairs of adjacent threads share -> broadcast).
    const float v = __ldg(A + (c << 6) + ((t & 127u) >> 1));
    const float4 v4 = make_float4(v, v, v, v);

    buf[t        ] = v4;
    buf[t + 256u ] = v4;
    buf[t + 512u ] = v4;
    buf[t + 768u ] = v4;

    __syncthreads();

    if (t == 0) {
        // Order generic-proxy STS before async-proxy bulk read.
        asm volatile("fence.proxy.async.shared::cta;" ::: "memory");
        const uint32_t s = smem_u32(buf);
        const float* dst = out + ((size_t)c << 12);   // c * 16 KB
        asm volatile(
            "cp.async.bulk.global.shared::cta.bulk_group [%0], [%1], %2;"
            :: "l"(dst), "r"(s), "n"(16384) : "memory");
        asm volatile("cp.async.bulk.commit_group;" ::: "memory");
        asm volatile("cp.async.bulk.wait_group 0;" ::: "memory");
    }
}

extern "C" void kernel_launch(void* const* d_in, const int* in_sizes, int n_in,
                              void* d_out, int out_size)
{
    const float* A = (const float*)d_in[0];   // (16,16,64,64) fp32
    float* out = (float*)d_out;               // (16,16,512,512) fp32

    // 16384 tiles x 16 KB = 256 MiB output
    expander_tma_kernel<<<16384, 256>>>(A, out);
}